// round 4
// baseline (speedup 1.0000x reference)
#include <cuda_runtime.h>

// SSD post-processing: decode + per-class greedy NMS.
//   loc_data  [8, 3000, 4]  f32
//   conf_data [8, 3000, 21] f32
//   priors    [3000, 4]     f32
//   out       [8, 21, 200, 5] f32  (score, x1, y1, x2, y2), zero-padded
//
// One CTA per (class, batch), grid (21, 8).
// Sort: bitonic on 4096 u64 keys; strides >=16 in smem (pair-expanded, all
//       threads active), strides <=8 fused into register-local passes
//       (16 keys/thread, XOR-swizzled smem layout for bank-conflict freedom).
// NMS:  candidate-driven (kept(j) <=> IoU vs every earlier kept <= thr).
//       Tiles of 256 (1 cand/thread): Phase A tests vs the accepted list in
//       parallel; then 8 subtiles of 32 are resolved warp-locally with
//       ballot/shfl -- ONE block barrier per subtile, none per acceptance.
//       Counts chained via s_cnts[sub] (write-before-barrier/read-after).

#define NP    3000
#define NPAD  4096
#define NC    21
#define TOPK  200
#define NT    256
#define NWARP (NT / 32)
#define EPT   (NPAD / NT)                   // 16 keys per thread
#define SW(i) ((i) ^ (((i) >> 4) & 15))     // bank swizzle for u64 keys[]

typedef unsigned long long ull;

__device__ __forceinline__ void cexch(ull& a, ull& b, bool desc) {
    if (desc ? (a < b) : (a > b)) { ull t = a; a = b; b = t; }
}

// reference-exact IoU (no FMA contraction)
__device__ __forceinline__ float iou_rn(float ax1, float ay1, float ax2, float ay2, float aa,
                                        float bx1, float by1, float bx2, float by2, float ba)
{
    float ltx = fmaxf(ax1, bx1);
    float lty = fmaxf(ay1, by1);
    float rbx = fminf(ax2, bx2);
    float rby = fminf(ay2, by2);
    float wx  = fmaxf(__fsub_rn(rbx, ltx), 0.0f);
    float wy  = fmaxf(__fsub_rn(rby, lty), 0.0f);
    float inter = __fmul_rn(wx, wy);
    float uni   = __fsub_rn(__fadd_rn(aa, ba), inter);
    return __fdiv_rn(inter, fmaxf(uni, 1e-12f));
}

__global__ __launch_bounds__(NT, 2) void ssd_post_kernel(
    const float* __restrict__ loc,
    const float* __restrict__ conf,
    const float* __restrict__ priors,
    float* __restrict__ out)
{
    __shared__ ull    keys[NPAD];     // 32 KB
    __shared__ float4 abox[TOPK];     // accepted boxes
    __shared__ float  aare[TOPK];     // accepted areas
    __shared__ int    s_cnts[NWARP];  // chained accepted-count per subtile
    __shared__ int    s_nvalid;

    const int c    = blockIdx.x;
    const int b    = blockIdx.y;
    const int tid  = threadIdx.x;
    const int lane = tid & 31;
    const int wix  = tid >> 5;

    float* outp = out + (size_t)(b * NC + c) * (TOPK * 5);
    for (int k = tid; k < TOPK * 5; k += NT) outp[k] = 0.0f;
    if (c == 0) return;  // background class: zeros only

    if (tid == 0) { s_nvalid = 0; s_cnts[NWARP - 1] = 0; }
    __syncthreads();

    // ---- build sort keys: (sortable(score) << 32) | ~idx  (stable desc) ----
    const float* confb = conf + (size_t)b * NP * NC + c;
    int myValid = 0;
    #pragma unroll
    for (int w = 0; w < EPT; ++w) {
        int p = tid + w * NT;
        ull key = 0ULL;                     // padding: below everything
        if (p < NP) {
            float s = confb[(size_t)p * NC];
            bool v = (s > 0.01f);
            myValid += v ? 1 : 0;
            if (!v) s = __int_as_float(0xff800000);  // -inf: sorts after valid
            unsigned u = __float_as_uint(s);
            u = (u & 0x80000000u) ? ~u : (u | 0x80000000u);
            key = ((ull)u << 32) | (unsigned)(~p);
        }
        keys[SW(p)] = key;
    }
    #pragma unroll
    for (int o = 16; o > 0; o >>= 1)
        myValid += __shfl_down_sync(0xffffffffu, myValid, o);
    if (lane == 0 && myValid) atomicAdd(&s_nvalid, myValid);
    __syncthreads();

    // ---- bitonic sort, descending ----
    // fused register-local stages k = 2,4,8,16 (strides all < 16)
    {
        const int base = tid * EPT;
        ull r[EPT];
        #pragma unroll
        for (int m = 0; m < EPT; ++m) r[m] = keys[SW(base + m)];
        #pragma unroll
        for (int k = 2; k <= 16; k <<= 1) {
            #pragma unroll
            for (int j = k >> 1; j >= 1; j >>= 1) {
                #pragma unroll
                for (int m = 0; m < EPT; ++m)
                    if (!(m & j))
                        cexch(r[m], r[m | j], ((base + m) & k) == 0);
            }
        }
        #pragma unroll
        for (int m = 0; m < EPT; ++m) keys[SW(base + m)] = r[m];
    }
    __syncthreads();

    for (int k = 32; k <= NPAD; k <<= 1) {
        // smem substages: strides j >= 16, pair-expanded (all threads active)
        for (int j = k >> 1; j >= 16; j >>= 1) {
            #pragma unroll
            for (int w = 0; w < NPAD / (2 * NT); ++w) {
                int p   = tid + w * NT;
                int i   = ((p & ~(j - 1)) << 1) | (p & (j - 1));
                int ixj = i | j;
                ull a  = keys[SW(i)];
                ull bb = keys[SW(ixj)];
                if (((i & k) == 0) ? (a < bb) : (a > bb)) {
                    keys[SW(i)] = bb; keys[SW(ixj)] = a;
                }
            }
            __syncthreads();
        }
        // register-local tail: strides 8,4,2,1 (direction uniform per thread)
        {
            const int  base = tid * EPT;
            const bool desc = ((base & k) == 0);
            ull r[EPT];
            #pragma unroll
            for (int m = 0; m < EPT; ++m) r[m] = keys[SW(base + m)];
            #pragma unroll
            for (int j = 8; j >= 1; j >>= 1) {
                #pragma unroll
                for (int m = 0; m < EPT; ++m)
                    if (!(m & j)) cexch(r[m], r[m | j], desc);
            }
            #pragma unroll
            for (int m = 0; m < EPT; ++m) keys[SW(base + m)] = r[m];
        }
        __syncthreads();
    }

    // ---- tiled candidate-driven NMS ----
    const int nvalid = s_nvalid;
    const float* locb = loc + (size_t)b * NP * 4;

    for (int tb = 0; tb < nvalid; tb += NT) {
        const int cnt0 = s_cnts[NWARP - 1];  // committed before last barrier
        if (cnt0 >= TOPK) break;             // uniform

        const int myIdx = tb + tid;
        bool myAlive = (myIdx < nvalid);

        // decode my candidate (exact reference op order)
        float mx1 = 0.f, my1 = 0.f, mx2 = 0.f, my2 = 0.f, mar = 0.f, ms = 0.f;
        if (myAlive) {
            ull key = keys[SW(myIdx)];
            int idx = (int)(~(unsigned)key);
            ms = __uint_as_float((unsigned)(key >> 32) & 0x7FFFFFFFu);  // valid => positive
            float4 l  = *(const float4*)(locb + (size_t)idx * 4);
            float4 pr = *(const float4*)(priors + (size_t)idx * 4);
            float cx = __fadd_rn(pr.x, __fmul_rn(__fmul_rn(l.x, 0.1f), pr.z));
            float cy = __fadd_rn(pr.y, __fmul_rn(__fmul_rn(l.y, 0.1f), pr.w));
            float w  = __fmul_rn(pr.z, expf(__fmul_rn(l.z, 0.2f)));
            float h  = __fmul_rn(pr.w, expf(__fmul_rn(l.w, 0.2f)));
            mx1 = __fsub_rn(cx, __fmul_rn(0.5f, w));
            my1 = __fsub_rn(cy, __fmul_rn(0.5f, h));
            mx2 = __fadd_rn(mx1, w);
            my2 = __fadd_rn(my1, h);
            mar = __fmul_rn(__fsub_rn(mx2, mx1), __fsub_rn(my2, my1));
        }

        // Phase A: test vs accepted[0..cnt0), early-out (no barrier needed:
        // reads are of state committed before the last barrier; concurrent
        // subtile-0 writes touch only indices >= cnt0)
        if (myAlive) {
            for (int j = 0; j < cnt0; ++j) {
                float4 ab = abox[j];
                if (iou_rn(mx1, my1, mx2, my2, mar,
                           ab.x, ab.y, ab.z, ab.w, aare[j]) > 0.45f) {
                    myAlive = false; break;
                }
            }
        }

        // Phase B: 8 subtiles, each resolved warp-locally; 1 barrier each
        #pragma unroll 1
        for (int sub = 0; sub < NWARP; ++sub) {
            if (wix == sub) {
                int cloc = (sub == 0) ? cnt0 : s_cnts[sub - 1];
                if (cloc < TOPK) {
                    // catch-up: accepts added by earlier subtiles of this tile
                    for (int j = cnt0; j < cloc && myAlive; ++j) {
                        float4 ab = abox[j];
                        if (iou_rn(mx1, my1, mx2, my2, mar,
                                   ab.x, ab.y, ab.z, ab.w, aare[j]) > 0.45f)
                            myAlive = false;
                    }
                    // warp-serial greedy resolution (score order = lane order)
                    unsigned mask = __ballot_sync(0xffffffffu, myAlive);
                    while (mask && cloc < TOPK) {
                        int L = __ffs(mask) - 1;
                        float cx1 = __shfl_sync(0xffffffffu, mx1, L);
                        float cy1 = __shfl_sync(0xffffffffu, my1, L);
                        float cx2 = __shfl_sync(0xffffffffu, mx2, L);
                        float cy2 = __shfl_sync(0xffffffffu, my2, L);
                        float car = __shfl_sync(0xffffffffu, mar, L);
                        if (lane == L) {
                            abox[cloc] = make_float4(mx1, my1, mx2, my2);
                            aare[cloc] = mar;
                            float* o = outp + cloc * 5;
                            o[0] = ms; o[1] = mx1; o[2] = my1; o[3] = mx2; o[4] = my2;
                            myAlive = false;
                        } else if (myAlive &&
                                   iou_rn(mx1, my1, mx2, my2, mar,
                                          cx1, cy1, cx2, cy2, car) > 0.45f) {
                            myAlive = false;
                        }
                        cloc++;
                        mask = __ballot_sync(0xffffffffu, myAlive);
                    }
                }
                if (lane == 0) s_cnts[sub] = cloc;
            }
            __syncthreads();  // publish abox/aare/s_cnts[sub] to next subtile
        }
    }
}

extern "C" void kernel_launch(void* const* d_in, const int* in_sizes, int n_in,
                              void* d_out, int out_size)
{
    const float* loc = nullptr;
    const float* conf = nullptr;
    const float* priors = nullptr;
    for (int i = 0; i < n_in; i++) {
        if (in_sizes[i] == 8 * NP * 4)       loc    = (const float*)d_in[i];
        else if (in_sizes[i] == 8 * NP * NC) conf   = (const float*)d_in[i];
        else if (in_sizes[i] == NP * 4)      priors = (const float*)d_in[i];
    }
    float* out = (float*)d_out;

    dim3 grid(NC, 8);
    ssd_post_kernel<<<grid, NT>>>(loc, conf, priors, out);
}